// round 16
// baseline (speedup 1.0000x reference)
#include <cuda_runtime.h>
#include <cuda_fp16.h>

#define L1D 16
#define IN_DIM 128
#define MAXN 65536
#define ZSTH 136     // padded smem row stride in HALVES (128 data + 8 pad)
#define NPB 32       // nodes per block in node_mlp
#define WROW 40      // combined weight row stride in halves (32 data + 8 pad)

// Scratch: node hidden activations in fp16 (allowed: __device__ globals)
__device__ __align__(16) __half g_h1h[MAXN * L1D];
__device__ __align__(16) __half g_h2h[MAXN * L1D];

// ---------------------------------------------------------------------------
// Kernel 1: per-node tiny MLP.  h1 = relu(z @ w1_l1), h2 = relu(z @ w2_l1)
// Block = 128 threads, 32 nodes. z and weights staged in smem as fp16
// (halves LDS traffic and smem footprint); fp32 scalar accumulate.
// smem: 32*136*2 + 2*16*136*2 = 17408 B.
// ---------------------------------------------------------------------------
__global__ __launch_bounds__(128) void node_mlp_kernel(
    const float* __restrict__ z,
    const float* __restrict__ w1,
    const float* __restrict__ w2,
    int n_nodes)
{
    __shared__ __half zsh[NPB * ZSTH];    // 8704 B
    __shared__ __half w1h[L1D * ZSTH];    // [col][k], 4352 B
    __shared__ __half w2h[L1D * ZSTH];

    const int tid = threadIdx.x;
    const int nbase = blockIdx.x * NPB;

    // stage weights (fp32 -> fp16), transposed to [col][k]
    for (int i = tid; i < IN_DIM * L1D; i += 128) {
        int k = i >> 4, c = i & 15;
        w1h[c * ZSTH + k] = __float2half_rn(w1[i]);
        w2h[c * ZSTH + k] = __float2half_rn(w2[i]);
    }
    // stage z tile (coalesced float4 reads -> packed half4 writes)
    {
        const float4* z4 = (const float4*)(z + (size_t)nbase * IN_DIM);
        int nval = n_nodes - nbase; if (nval > NPB) nval = NPB;
        for (int i = tid; i < nval * (IN_DIM / 4); i += 128) {
            int r = i >> 5, q = i & 31;
            float4 v = z4[i];
            __half2 h0 = __float22half2_rn(make_float2(v.x, v.y));
            __half2 h1 = __float22half2_rn(make_float2(v.z, v.w));
            *(uint2*)(zsh + r * ZSTH + q * 4) =
                make_uint2(*(unsigned*)&h0, *(unsigned*)&h1);
        }
    }
    __syncthreads();

    const int col  = tid & 15;
    const int slot = (tid >> 4) & 1;
    const int warp = tid >> 5;
    const int nloc0 = warp * 8 + slot * 4;

    float a1[4] = {0.f, 0.f, 0.f, 0.f};
    float a2[4] = {0.f, 0.f, 0.f, 0.f};

    #pragma unroll 4
    for (int k = 0; k < IN_DIM; k += 8) {
        uint4 wa = *(const uint4*)(w1h + col * ZSTH + k);
        uint4 wb = *(const uint4*)(w2h + col * ZSTH + k);
        float2 waf[4], wbf[4];
        #pragma unroll
        for (int m = 0; m < 4; m++) {
            waf[m] = __half22float2(((const __half2*)&wa)[m]);
            wbf[m] = __half22float2(((const __half2*)&wb)[m]);
        }
        #pragma unroll
        for (int j = 0; j < 4; j++) {
            uint4 zv = *(const uint4*)(zsh + (nloc0 + j) * ZSTH + k);
            #pragma unroll
            for (int m = 0; m < 4; m++) {
                float2 zf = __half22float2(((const __half2*)&zv)[m]);
                a1[j] = fmaf(zf.x, waf[m].x, a1[j]);
                a1[j] = fmaf(zf.y, waf[m].y, a1[j]);
                a2[j] = fmaf(zf.x, wbf[m].x, a2[j]);
                a2[j] = fmaf(zf.y, wbf[m].y, a2[j]);
            }
        }
    }

    #pragma unroll
    for (int j = 0; j < 4; j++) {
        int node = nbase + nloc0 + j;
        if (node < n_nodes) {
            g_h1h[node * L1D + col] = __float2half_rn(fmaxf(a1[j], 0.f));
            g_h2h[node * L1D + col] = __float2half_rn(fmaxf(a2[j], 0.f));
        }
    }
}

// ---------------------------------------------------------------------------
// Kernel 2: per-edge scoring, 4 lanes per edge, consecutive edge pair per
// group-iteration; role-split vector index loads; combined fp16 weight rows;
// paired float2 store. (Exact measured-best version.)
// ---------------------------------------------------------------------------
__global__ __launch_bounds__(256) void edge_kernel(
    const float* __restrict__ w1_l2,
    const float* __restrict__ w2_l2,
    const void* __restrict__ ei,
    const void* __restrict__ et,
    float* __restrict__ out,
    int n_edges, int n_etype)
{
    extern __shared__ __half wch[];   // [n_etype][WROW]
    __shared__ int s_is64;

    if (threadIdx.x < 32) {
        unsigned v = ((const unsigned*)ei)[2 * threadIdx.x + 1];
        unsigned any = __ballot_sync(0xFFFFFFFFu, v != 0u);
        if (threadIdx.x == 0) s_is64 = (any == 0u) ? 1 : 0;
    }
    for (int i = threadIdx.x; i < n_etype * 4; i += blockDim.x) {
        int t = i >> 2, q = i & 3;
        const float4* src = (q < 2) ? (const float4*)w1_l2 : (const float4*)w2_l2;
        int qq = q & 1;
        float4 fa = src[t * 4 + qq * 2];
        float4 fb = src[t * 4 + qq * 2 + 1];
        __half2 h0 = __float22half2_rn(make_float2(fa.x, fa.y));
        __half2 h1 = __float22half2_rn(make_float2(fa.z, fa.w));
        __half2 h2 = __float22half2_rn(make_float2(fb.x, fb.y));
        __half2 h3 = __float22half2_rn(make_float2(fb.z, fb.w));
        uint4 pk = make_uint4(*(unsigned*)&h0, *(unsigned*)&h1,
                              *(unsigned*)&h2, *(unsigned*)&h3);
        *(uint4*)(wch + t * WROW + q * 8) = pk;
    }
    __syncthreads();

    const int is64 = s_is64;
    const bool even = (n_edges & 1) == 0;
    const int sub = threadIdx.x & 3;
    const int lane_group = (threadIdx.x >> 2) & 7;
    const int group0 = (blockIdx.x * blockDim.x + threadIdx.x) >> 2;
    const int G = (gridDim.x * blockDim.x) >> 2;
    const int warp_base0 = group0 - lane_group;
    const int npairs = (n_edges + 1) >> 1;
    const int pmax = npairs - 1;
    const int emax = n_edges - 1;

    const __half* htab = (sub < 2) ? g_h1h : g_h2h;
    const int hq = (sub & 1) * 8;
    const size_t noff = (sub < 2) ? 0 : (size_t)n_edges;

    const long long* p64 = (const long long*)ei + noff;
    const int*       p32 = (const int*)ei + noff;
    const long long* t64 = (const long long*)et;
    const int*       t32 = (const int*)et;

    for (int base = warp_base0; base < npairs; base += G) {
        int pp = base + lane_group;
        int pc = pp < npairs ? pp : pmax;
        int e0 = 2 * pc;

        int nA, nB, tA, tB;
        if (is64) {
            if (even) {
                longlong2 nv = *(const longlong2*)(p64 + e0);
                longlong2 tv = *(const longlong2*)(t64 + e0);
                nA = (int)nv.x; nB = (int)nv.y;
                tA = (int)tv.x; tB = (int)tv.y;
            } else {
                int eB = (e0 + 1 < n_edges) ? e0 + 1 : emax;
                nA = (int)__ldg(p64 + e0); nB = (int)__ldg(p64 + eB);
                tA = (int)__ldg(t64 + e0); tB = (int)__ldg(t64 + eB);
            }
        } else {
            if (even) {
                int2 nv = *(const int2*)(p32 + e0);
                int2 tv = *(const int2*)(t32 + e0);
                nA = nv.x; nB = nv.y;
                tA = tv.x; tB = tv.y;
            } else {
                int eB = (e0 + 1 < n_edges) ? e0 + 1 : emax;
                nA = __ldg(p32 + e0); nB = __ldg(p32 + eB);
                tA = __ldg(t32 + e0); tB = __ldg(t32 + eB);
            }
        }

        uint4 hv0 = *(const uint4*)(htab + nA * L1D + hq);
        uint4 hv1 = *(const uint4*)(htab + nB * L1D + hq);
        uint4 wv0 = *(const uint4*)(wch + tA * WROW + sub * 8);
        uint4 wv1 = *(const uint4*)(wch + tB * WROW + sub * 8);

        float acc0 = 0.f, acc1 = 0.f;
        const unsigned* hp0 = (const unsigned*)&hv0;
        const unsigned* wp0 = (const unsigned*)&wv0;
        const unsigned* hp1 = (const unsigned*)&hv1;
        const unsigned* wp1 = (const unsigned*)&wv1;
        #pragma unroll
        for (int k = 0; k < 4; k++) {
            float2 ha = __half22float2(*(const __half2*)(hp0 + k));
            float2 wa = __half22float2(*(const __half2*)(wp0 + k));
            acc0 = fmaf(ha.x, wa.x, acc0);
            acc0 = fmaf(ha.y, wa.y, acc0);
            float2 hb = __half22float2(*(const __half2*)(hp1 + k));
            float2 wb = __half22float2(*(const __half2*)(wp1 + k));
            acc1 = fmaf(hb.x, wb.x, acc1);
            acc1 = fmaf(hb.y, wb.y, acc1);
        }

        acc0 += __shfl_xor_sync(0xFFFFFFFFu, acc0, 1);
        acc1 += __shfl_xor_sync(0xFFFFFFFFu, acc1, 1);
        acc0 += __shfl_xor_sync(0xFFFFFFFFu, acc0, 2);
        acc1 += __shfl_xor_sync(0xFFFFFFFFu, acc1, 2);

        if (sub == 0) {
            float o0 = 1.f / (1.f + __expf(-acc0));
            float o1 = 1.f / (1.f + __expf(-acc1));
            if (e0 + 1 < n_edges) {
                *(float2*)(out + e0) = make_float2(o0, o1);
            } else {
                out[e0] = o0;
            }
        }
    }
}

// ---------------------------------------------------------------------------
// Launch. Inputs (metadata order): z, w1_l1, w1_l2, w2_l1, w2_l2,
// edge_index [2,E], edge_type [E].  Output: float32 [E].
// ---------------------------------------------------------------------------
extern "C" void kernel_launch(void* const* d_in, const int* in_sizes, int n_in,
                              void* d_out, int out_size) {
    const float* z     = (const float*)d_in[0];
    const float* w1_l1 = (const float*)d_in[1];
    const float* w1_l2 = (const float*)d_in[2];
    const float* w2_l1 = (const float*)d_in[3];
    const float* w2_l2 = (const float*)d_in[4];
    const void*  ei    = d_in[5];
    const void*  et    = d_in[6];
    float* out = (float*)d_out;

    int n_nodes = in_sizes[0] / IN_DIM;
    int n_etype = in_sizes[2] / L1D;
    int n_edges = out_size;

    int nb1 = (n_nodes + NPB - 1) / NPB;
    node_mlp_kernel<<<nb1, 128>>>(z, w1_l1, w2_l1, n_nodes);

    size_t smem2 = (size_t)n_etype * WROW * sizeof(__half);
    edge_kernel<<<1036, 256, smem2>>>(w1_l2, w2_l2, ei, et, out, n_edges, n_etype);
}